// round 14
// baseline (speedup 1.0000x reference)
#include <cuda_runtime.h>
#include <cuda_bf16.h>
#include <cstdint>

// ---------------- problem dims ----------------
#define MDIM 8192
#define NDIM 4096
#define KDIM 4096

// ---------------- tiling ----------------
#define BM 128
#define BN 128
#define BK 64                              // K elements per chunk (bf16): 128B per row
#define ROWB 144                           // padded row stride (128B data + 16B pad)
#define STAGES 3
#define NCHUNK (KDIM / BK)                 // 64
#define A_STAGE (BM * ROWB)                // 18432 B
#define B_STAGE (BN * ROWB)                // 18432 B
#define STAGE_BYTES (A_STAGE + B_STAGE)    // 36864 B
#define SMEM_DYN (STAGES * STAGE_BYTES)    // 110592 B -> 2 CTAs/SM
#define THREADS 256                        // 8 warps, warp tile 32x64

// ---------------- bf16 staging (static device globals: no allocation) ----------------
__device__ __nv_bfloat16 g_A[(size_t)MDIM * KDIM];   // 64 MB
__device__ __nv_bfloat16 g_B[(size_t)NDIM * KDIM];   // 32 MB

// ---------------- PTX helpers (base-ISA: cp.async / ldmatrix / mma.sync bf16) -------
__device__ __forceinline__ uint32_t smem_u32(const void* p) {
    uint32_t a;
    asm("{ .reg .u64 t; cvta.to.shared.u64 t, %1; cvt.u32.u64 %0, t; }" : "=r"(a) : "l"(p));
    return a;
}

__device__ __forceinline__ void cp16(uint32_t dst, const void* src) {
    asm volatile("cp.async.cg.shared.global [%0], [%1], 16;" :: "r"(dst), "l"(src));
}
__device__ __forceinline__ void cp_commit() {
    asm volatile("cp.async.commit_group;" ::: "memory");
}
template <int N>
__device__ __forceinline__ void cp_wait() {
    asm volatile("cp.async.wait_group %0;" :: "n"(N) : "memory");
}

__device__ __forceinline__ void ldsm4(uint32_t* r, uint32_t addr) {
    asm volatile("ldmatrix.sync.aligned.m8n8.x4.shared.b16 {%0,%1,%2,%3}, [%4];"
                 : "=r"(r[0]), "=r"(r[1]), "=r"(r[2]), "=r"(r[3])
                 : "r"(addr));
}

__device__ __forceinline__ void mma_bf16(float* d, const uint32_t* a, const uint32_t* b) {
    asm volatile("mma.sync.aligned.m16n8k16.row.col.f32.bf16.bf16.f32 "
                 "{%0,%1,%2,%3}, {%4,%5,%6,%7}, {%8,%9}, {%0,%1,%2,%3};"
                 : "+f"(d[0]), "+f"(d[1]), "+f"(d[2]), "+f"(d[3])
                 : "r"(a[0]), "r"(a[1]), "r"(a[2]), "r"(a[3]), "r"(b[0]), "r"(b[1]));
}

// ---------------- fused conversion kernel (int8-valued -> bf16, exact) ----------------
#define CVT_XBLOCKS 4096
#define CVT_WBLOCKS 2048

__global__ void __launch_bounds__(512) cvt_fused_kernel(const int4* __restrict__ x,
                                                        const float4* __restrict__ w) {
    const unsigned b = blockIdx.x;
    if (b < CVT_XBLOCKS) {
        const size_t base = (size_t)b * 2048 + threadIdx.x;
        int4 v[4];
        #pragma unroll
        for (int k = 0; k < 4; k++) v[k] = x[base + (size_t)k * 512];
        #pragma unroll
        for (int k = 0; k < 4; k++) {
            union { __nv_bfloat162 h2[2]; uint2 u; } o;
            o.h2[0] = __floats2bfloat162_rn((float)v[k].x, (float)v[k].y);
            o.h2[1] = __floats2bfloat162_rn((float)v[k].z, (float)v[k].w);
            reinterpret_cast<uint2*>(g_A)[base + (size_t)k * 512] = o.u;
        }
    } else {
        const size_t base = (size_t)(b - CVT_XBLOCKS) * 2048 + threadIdx.x;
        float4 v[4];
        #pragma unroll
        for (int k = 0; k < 4; k++) v[k] = w[base + (size_t)k * 512];
        #pragma unroll
        for (int k = 0; k < 4; k++) {
            union { __nv_bfloat162 h2[2]; uint2 u; } o;
            o.h2[0] = __floats2bfloat162_rn(v[k].x, v[k].y);
            o.h2[1] = __floats2bfloat162_rn(v[k].z, v[k].w);
            reinterpret_cast<uint2*>(g_B)[base + (size_t)k * 512] = o.u;
        }
    }
}

// ---------------- GEMM kernel ----------------
__device__ __forceinline__ int clip8(int v) {
    return v < -128 ? -128 : (v > 127 ? 127 : v);
}

__global__ void __launch_bounds__(THREADS, 2)
hmma_gemm_kernel(const float* __restrict__ bias,
                 const float* __restrict__ alpha_p,
                 float* __restrict__ out) {
    extern __shared__ int8_t smem[];
    const uint32_t sbase = smem_u32(smem);

    const int tid  = threadIdx.x;
    const int lane = tid & 31;
    const int wid  = tid >> 5;       // 0..7
    const int wm   = wid >> 1;       // 0..3  (M warps, 32 rows each)
    const int wn   = wid & 1;        // 0..1  (N warps, 64 cols each)
    const int m_base = blockIdx.y * BM;
    const int n_base = blockIdx.x * BN;

    float acc[2][8][4];
    #pragma unroll
    for (int i = 0; i < 2; i++)
        #pragma unroll
        for (int j = 0; j < 8; j++)
            #pragma unroll
            for (int k = 0; k < 4; k++) acc[i][j][k] = 0.0f;

    // --- ldmatrix per-thread address components (padded 144B rows) ---
    const uint32_t arow   = (uint32_t)(wm * 32 + (lane & 15));
    const uint32_t akb_hi = (uint32_t)(lane >> 4);                 // 0/1 (8-element k half)
    const uint32_t a_off  = arow * ROWB + akb_hi * 16u;           // + s*32 + i*(16*ROWB)

    const uint32_t brow   = (uint32_t)(wn * 64 + (lane & 7) + ((lane >> 4) << 3));
    const uint32_t bkb_hi = (uint32_t)((lane >> 3) & 1);
    const uint32_t b_off  = brow * ROWB + bkb_hi * 16u;           // + s*32 + j*(16*ROWB)

    // --- one slice of a stage load: 2 chunks (of this thread's 8) ---
    auto load_slice = [&](int kc, int st, int slice) {
        const uint32_t sb = sbase + (uint32_t)st * STAGE_BYTES;
        const int kel = kc * BK;
        #pragma unroll
        for (int q = 0; q < 2; q++) {
            int ch = tid + THREADS * (2 * slice + q);
            if (ch < 1024) {   // A: 1024 chunks (uniform: slice<2)
                int row = ch >> 3, kb = ch & 7;
                cp16(sb + (uint32_t)row * ROWB + (uint32_t)kb * 16u,
                     g_A + (size_t)(m_base + row) * KDIM + kel + kb * 8);
            } else {           // B: 1024 chunks
                int c2 = ch - 1024;
                int row = c2 >> 3, kb = c2 & 7;
                cp16(sb + A_STAGE + (uint32_t)row * ROWB + (uint32_t)kb * 16u,
                     g_B + (size_t)(n_base + row) * KDIM + kel + kb * 8);
            }
        }
    };
    auto load_stage = [&](int kc, int st) {
        #pragma unroll
        for (int i = 0; i < 4; i++) load_slice(kc, st, i);
        cp_commit();
    };

    // --- prologue: 2 stages in flight ---
    load_stage(0, 0);
    load_stage(1, 1);

    // --- mainloop: DMA slices interleaved + A and B fragment double buffers ---
    int st = 0;
    for (int c = 0; c < NCHUNK; c++) {
        cp_wait<1>();
        __syncthreads();

        const bool do_load = (c + 2 < NCHUNK);
        const int  ld_st   = (c + 2) % STAGES;   // slot last read in iter c-1; safe after barrier

        const uint32_t sb = sbase + (uint32_t)st * STAGE_BYTES;

        // A double buffer: preload s=0 fragments
        uint32_t af[2][2][4];                     // [buf][m-tile][regs]
        ldsm4(af[0][0], sb + a_off);
        ldsm4(af[0][1], sb + a_off + 16u * ROWB);

        #pragma unroll
        for (int s = 0; s < 4; s++) {                      // 4 k16 steps per chunk
            const int cur = s & 1, nxt = cur ^ 1;

            // B double buffer: load bf[j+1] before consuming bf[j]'s mma burst
            uint32_t bf[2][4];
            ldsm4(bf[0], sb + A_STAGE + b_off + (uint32_t)s * 32u);
            #pragma unroll
            for (int j = 0; j < 4; j++) {                  // 4 n16 pairs = 64 n
                if (j < 3)
                    ldsm4(bf[(j + 1) & 1],
                          sb + A_STAGE + b_off + (uint32_t)s * 32u + (uint32_t)(j + 1) * (16u * ROWB));
                if (j == 0 && s < 3) {                     // prefetch next s's A under this burst
                    ldsm4(af[nxt][0], sb + a_off + (uint32_t)(s + 1) * 32u);
                    ldsm4(af[nxt][1], sb + a_off + (uint32_t)(s + 1) * 32u + 16u * ROWB);
                }
                const uint32_t* b = bf[j & 1];
                mma_bf16(acc[0][2 * j],     af[cur][0], b);
                mma_bf16(acc[0][2 * j + 1], af[cur][0], b + 2);
                mma_bf16(acc[1][2 * j],     af[cur][1], b);
                mma_bf16(acc[1][2 * j + 1], af[cur][1], b + 2);
            }
            if (do_load) load_slice(c + 2, ld_st, s);      // 2 cp16/thread, spread evenly
        }
        cp_commit();   // exactly one commit per chunk (possibly empty group) keeps counting aligned

        st = (st + 1 == STAGES) ? 0 : st + 1;
    }

    // --- epilogue: y = clip(round_half_even(acc*alpha + bias)), stored as FLOAT32 ---
    const float alphav = *alpha_p;
    const int g = lane >> 2, t = lane & 3;
    #pragma unroll
    for (int i = 0; i < 2; i++) {
        const size_t row0 = (size_t)(m_base + wm * 32 + i * 16 + g);
        #pragma unroll
        for (int j = 0; j < 8; j++) {
            const int nc = n_base + wn * 64 + j * 8 + 2 * t;
            const float b0 = __ldg(bias + nc);
            const float b1 = __ldg(bias + nc + 1);
            const float* a = acc[i][j];
            int v0 = clip8(__float2int_rn(__fadd_rn(__fmul_rn(a[0], alphav), b0)));
            int v1 = clip8(__float2int_rn(__fadd_rn(__fmul_rn(a[1], alphav), b1)));
            int v2 = clip8(__float2int_rn(__fadd_rn(__fmul_rn(a[2], alphav), b0)));
            int v3 = clip8(__float2int_rn(__fadd_rn(__fmul_rn(a[3], alphav), b1)));
            float2 lo = make_float2((float)v0, (float)v1);
            float2 hi = make_float2((float)v2, (float)v3);
            *reinterpret_cast<float2*>(out + row0 * NDIM + nc) = lo;
            *reinterpret_cast<float2*>(out + (row0 + 8) * NDIM + nc) = hi;
        }
    }
}

// ---------------- host launch ----------------
extern "C" void kernel_launch(void* const* d_in, const int* in_sizes, int n_in,
                              void* d_out, int out_size) {
    const int*   x     = (const int*)d_in[0];
    const float* w     = (const float*)d_in[1];
    const float* bias  = (const float*)d_in[2];
    const float* alpha = (const float*)d_in[3];
    float*       out   = (float*)d_out;

    // single fused bf16 conversion launch (x + w)
    cvt_fused_kernel<<<CVT_XBLOCKS + CVT_WBLOCKS, 512>>>((const int4*)x, (const float4*)w);

    // set every call (non-stream API, capture-safe; no static guards per harness rules)
    cudaFuncSetAttribute(hmma_gemm_kernel,
                         cudaFuncAttributeMaxDynamicSharedMemorySize, SMEM_DYN);

    dim3 grid(NDIM / BN, MDIM / BM);   // (32, 64) = 2048 CTAs
    hmma_gemm_kernel<<<grid, THREADS, SMEM_DYN>>>(bias, alpha, out);
}

// round 15
// speedup vs baseline: 1.0201x; 1.0201x over previous
#include <cuda_runtime.h>
#include <cuda_bf16.h>
#include <cstdint>

// ---------------- problem dims ----------------
#define MDIM 8192
#define NDIM 4096
#define KDIM 4096

// ---------------- tiling ----------------
#define BM 128
#define BN 128
#define BK 64                              // K elements per chunk (bf16): 128B per row
#define ROWB 144                           // padded row stride (128B data + 16B pad)
#define STAGES 3
#define NCHUNK (KDIM / BK)                 // 64
#define A_STAGE (BM * ROWB)                // 18432 B
#define B_STAGE (BN * ROWB)                // 18432 B
#define STAGE_BYTES (A_STAGE + B_STAGE)    // 36864 B
#define SMEM_DYN (STAGES * STAGE_BYTES)    // 110592 B -> 2 CTAs/SM
#define THREADS 256                        // 8 warps, warp tile 32x64

// ---------------- bf16 staging (static device globals: no allocation) ----------------
__device__ __nv_bfloat16 g_A[(size_t)MDIM * KDIM];   // 64 MB
__device__ __nv_bfloat16 g_B[(size_t)NDIM * KDIM];   // 32 MB

// ---------------- PTX helpers (base-ISA: cp.async / ldmatrix / mma.sync bf16) -------
__device__ __forceinline__ uint32_t smem_u32(const void* p) {
    uint32_t a;
    asm("{ .reg .u64 t; cvta.to.shared.u64 t, %1; cvt.u32.u64 %0, t; }" : "=r"(a) : "l"(p));
    return a;
}

__device__ __forceinline__ void cp16(uint32_t dst, const void* src) {
    asm volatile("cp.async.cg.shared.global [%0], [%1], 16;" :: "r"(dst), "l"(src));
}
__device__ __forceinline__ void cp_commit() {
    asm volatile("cp.async.commit_group;" ::: "memory");
}
template <int N>
__device__ __forceinline__ void cp_wait() {
    asm volatile("cp.async.wait_group %0;" :: "n"(N) : "memory");
}

__device__ __forceinline__ void ldsm4(uint32_t* r, uint32_t addr) {
    asm volatile("ldmatrix.sync.aligned.m8n8.x4.shared.b16 {%0,%1,%2,%3}, [%4];"
                 : "=r"(r[0]), "=r"(r[1]), "=r"(r[2]), "=r"(r[3])
                 : "r"(addr));
}

__device__ __forceinline__ void mma_bf16(float* d, const uint32_t* a, const uint32_t* b) {
    asm volatile("mma.sync.aligned.m16n8k16.row.col.f32.bf16.bf16.f32 "
                 "{%0,%1,%2,%3}, {%4,%5,%6,%7}, {%8,%9}, {%0,%1,%2,%3};"
                 : "+f"(d[0]), "+f"(d[1]), "+f"(d[2]), "+f"(d[3])
                 : "r"(a[0]), "r"(a[1]), "r"(a[2]), "r"(a[3]), "r"(b[0]), "r"(b[1]));
}

// ---------------- fused conversion kernel (int8-valued -> bf16, exact) ----------------
#define CVT_XBLOCKS 4096
#define CVT_WBLOCKS 2048

__global__ void __launch_bounds__(512) cvt_fused_kernel(const int4* __restrict__ x,
                                                        const float4* __restrict__ w) {
    const unsigned b = blockIdx.x;
    if (b < CVT_XBLOCKS) {
        const size_t base = (size_t)b * 2048 + threadIdx.x;
        int4 v[4];
        #pragma unroll
        for (int k = 0; k < 4; k++) v[k] = x[base + (size_t)k * 512];
        #pragma unroll
        for (int k = 0; k < 4; k++) {
            union { __nv_bfloat162 h2[2]; uint2 u; } o;
            o.h2[0] = __floats2bfloat162_rn((float)v[k].x, (float)v[k].y);
            o.h2[1] = __floats2bfloat162_rn((float)v[k].z, (float)v[k].w);
            reinterpret_cast<uint2*>(g_A)[base + (size_t)k * 512] = o.u;
        }
    } else {
        const size_t base = (size_t)(b - CVT_XBLOCKS) * 2048 + threadIdx.x;
        float4 v[4];
        #pragma unroll
        for (int k = 0; k < 4; k++) v[k] = w[base + (size_t)k * 512];
        #pragma unroll
        for (int k = 0; k < 4; k++) {
            union { __nv_bfloat162 h2[2]; uint2 u; } o;
            o.h2[0] = __floats2bfloat162_rn(v[k].x, v[k].y);
            o.h2[1] = __floats2bfloat162_rn(v[k].z, v[k].w);
            reinterpret_cast<uint2*>(g_B)[base + (size_t)k * 512] = o.u;
        }
    }
}

// ---------------- GEMM kernel ----------------
__device__ __forceinline__ int clip8(int v) {
    return v < -128 ? -128 : (v > 127 ? 127 : v);
}

__global__ void __launch_bounds__(THREADS, 2)
hmma_gemm_kernel(const float* __restrict__ bias,
                 const float* __restrict__ alpha_p,
                 float* __restrict__ out) {
    extern __shared__ int8_t smem[];
    const uint32_t sbase = smem_u32(smem);

    const int tid  = threadIdx.x;
    const int lane = tid & 31;
    const int wid  = tid >> 5;       // 0..7
    const int wm   = wid >> 1;       // 0..3  (M warps, 32 rows each)
    const int wn   = wid & 1;        // 0..1  (N warps, 64 cols each)
    const int m_base = blockIdx.y * BM;
    const int n_base = blockIdx.x * BN;

    float acc[2][8][4];
    #pragma unroll
    for (int i = 0; i < 2; i++)
        #pragma unroll
        for (int j = 0; j < 8; j++)
            #pragma unroll
            for (int k = 0; k < 4; k++) acc[i][j][k] = 0.0f;

    // --- ldmatrix per-thread address components (padded 144B rows) ---
    const uint32_t arow   = (uint32_t)(wm * 32 + (lane & 15));
    const uint32_t akb_hi = (uint32_t)(lane >> 4);                 // 0/1 (8-element k half)
    const uint32_t a_off  = arow * ROWB + akb_hi * 16u;           // + s*32 + i*(16*ROWB)

    const uint32_t brow   = (uint32_t)(wn * 64 + (lane & 7) + ((lane >> 4) << 3));
    const uint32_t bkb_hi = (uint32_t)((lane >> 3) & 1);
    const uint32_t b_off  = brow * ROWB + bkb_hi * 16u;           // + s*32 + j*(16*ROWB)

    // --- one slice of a stage load: 2 chunks (of this thread's 8) ---
    auto load_slice = [&](int kc, int st, int slice) {
        const uint32_t sb = sbase + (uint32_t)st * STAGE_BYTES;
        const int kel = kc * BK;
        #pragma unroll
        for (int q = 0; q < 2; q++) {
            int ch = tid + THREADS * (2 * slice + q);
            if (ch < 1024) {   // A: 1024 chunks (uniform: slice<2)
                int row = ch >> 3, kb = ch & 7;
                cp16(sb + (uint32_t)row * ROWB + (uint32_t)kb * 16u,
                     g_A + (size_t)(m_base + row) * KDIM + kel + kb * 8);
            } else {           // B: 1024 chunks
                int c2 = ch - 1024;
                int row = c2 >> 3, kb = c2 & 7;
                cp16(sb + A_STAGE + (uint32_t)row * ROWB + (uint32_t)kb * 16u,
                     g_B + (size_t)(n_base + row) * KDIM + kel + kb * 8);
            }
        }
    };
    auto load_stage = [&](int kc, int st) {
        #pragma unroll
        for (int i = 0; i < 4; i++) load_slice(kc, st, i);
        cp_commit();
    };

    // --- prologue: 2 stages in flight ---
    load_stage(0, 0);
    load_stage(1, 1);

    // --- mainloop: DMA slices interleaved + B-fragment double buffer (R13 winner) ---
    int st = 0;
    for (int c = 0; c < NCHUNK; c++) {
        cp_wait<1>();
        __syncthreads();

        const bool do_load = (c + 2 < NCHUNK);
        const int  ld_st   = (c + 2) % STAGES;   // slot last read in iter c-1; safe after barrier

        const uint32_t sb     = sbase + (uint32_t)st * STAGE_BYTES;
        const uint32_t a_base = sb + a_off;                     // hoisted invariants
        const uint32_t b_base = sb + A_STAGE + b_off;

        #pragma unroll
        for (int s = 0; s < 4; s++) {                      // 4 k16 steps per chunk
            uint32_t af[2][4];
            uint32_t bf[2][4];
            // issue order: af[0], bf[0] (first mma's operands) before af[1]
            ldsm4(af[0], a_base + (uint32_t)s * 32u);
            ldsm4(bf[0], b_base + (uint32_t)s * 32u);
            ldsm4(af[1], a_base + (uint32_t)s * 32u + 16u * ROWB);
            #pragma unroll
            for (int j = 0; j < 4; j++) {                  // 4 n16 pairs = 64 n
                if (j < 3)
                    ldsm4(bf[(j + 1) & 1],
                          b_base + (uint32_t)s * 32u + (uint32_t)(j + 1) * (16u * ROWB));
                const uint32_t* b = bf[j & 1];
                mma_bf16(acc[0][2 * j],     af[0], b);
                mma_bf16(acc[0][2 * j + 1], af[0], b + 2);
                mma_bf16(acc[1][2 * j],     af[1], b);
                mma_bf16(acc[1][2 * j + 1], af[1], b + 2);
            }
            if (do_load) load_slice(c + 2, ld_st, s);      // 2 cp16/thread, spread evenly
        }
        cp_commit();   // exactly one commit per chunk (possibly empty group) keeps counting aligned

        st = (st + 1 == STAGES) ? 0 : st + 1;
    }

    // --- epilogue: y = clip(round_half_even(acc*alpha + bias)), stored as FLOAT32 ---
    const float alphav = *alpha_p;
    const int g = lane >> 2, t = lane & 3;
    #pragma unroll
    for (int i = 0; i < 2; i++) {
        const size_t row0 = (size_t)(m_base + wm * 32 + i * 16 + g);
        #pragma unroll
        for (int j = 0; j < 8; j++) {
            const int nc = n_base + wn * 64 + j * 8 + 2 * t;
            const float b0 = __ldg(bias + nc);
            const float b1 = __ldg(bias + nc + 1);
            const float* a = acc[i][j];
            int v0 = clip8(__float2int_rn(__fadd_rn(__fmul_rn(a[0], alphav), b0)));
            int v1 = clip8(__float2int_rn(__fadd_rn(__fmul_rn(a[1], alphav), b1)));
            int v2 = clip8(__float2int_rn(__fadd_rn(__fmul_rn(a[2], alphav), b0)));
            int v3 = clip8(__float2int_rn(__fadd_rn(__fmul_rn(a[3], alphav), b1)));
            float2 lo = make_float2((float)v0, (float)v1);
            float2 hi = make_float2((float)v2, (float)v3);
            *reinterpret_cast<float2*>(out + row0 * NDIM + nc) = lo;
            *reinterpret_cast<float2*>(out + (row0 + 8) * NDIM + nc) = hi;
        }
    }
}

// ---------------- host launch ----------------
extern "C" void kernel_launch(void* const* d_in, const int* in_sizes, int n_in,
                              void* d_out, int out_size) {
    const int*   x     = (const int*)d_in[0];
    const float* w     = (const float*)d_in[1];
    const float* bias  = (const float*)d_in[2];
    const float* alpha = (const float*)d_in[3];
    float*       out   = (float*)d_out;

    // single fused bf16 conversion launch (x + w)
    cvt_fused_kernel<<<CVT_XBLOCKS + CVT_WBLOCKS, 512>>>((const int4*)x, (const float4*)w);

    // set every call (non-stream API, capture-safe; no static guards per harness rules)
    cudaFuncSetAttribute(hmma_gemm_kernel,
                         cudaFuncAttributeMaxDynamicSharedMemorySize, SMEM_DYN);

    dim3 grid(NDIM / BN, MDIM / BM);   // (32, 64) = 2048 CTAs
    hmma_gemm_kernel<<<grid, THREADS, SMEM_DYN>>>(bias, alpha, out);
}

// round 16
// speedup vs baseline: 1.0756x; 1.0545x over previous
#include <cuda_runtime.h>
#include <cuda_bf16.h>
#include <cstdint>

// ---------------- problem dims ----------------
#define MDIM 8192
#define NDIM 4096
#define KDIM 4096

// ---------------- tiling ----------------
#define BM 128
#define BN 128
#define BK 64                              // K elements per chunk (bf16): 128B per row
#define ROWB 144                           // padded row stride (128B data + 16B pad)
#define STAGES 3
#define NCHUNK (KDIM / BK)                 // 64
#define A_STAGE (BM * ROWB)                // 18432 B
#define B_STAGE (BN * ROWB)                // 18432 B
#define STAGE_BYTES (A_STAGE + B_STAGE)    // 36864 B
#define SMEM_DYN (STAGES * STAGE_BYTES)    // 110592 B -> 2 CTAs/SM
#define THREADS 256                        // 8 warps, warp tile 32x64

// ---------------- bf16 staging (static device globals: no allocation) ----------------
__device__ __nv_bfloat16 g_A[(size_t)MDIM * KDIM];   // 64 MB
__device__ __nv_bfloat16 g_B[(size_t)NDIM * KDIM];   // 32 MB

// ---------------- PTX helpers (base-ISA: cp.async / ldmatrix / mma.sync / mbarrier) --
__device__ __forceinline__ uint32_t smem_u32(const void* p) {
    uint32_t a;
    asm("{ .reg .u64 t; cvta.to.shared.u64 t, %1; cvt.u32.u64 %0, t; }" : "=r"(a) : "l"(p));
    return a;
}

__device__ __forceinline__ void cp16(uint32_t dst, const void* src) {
    asm volatile("cp.async.cg.shared.global [%0], [%1], 16;" :: "r"(dst), "l"(src));
}

__device__ __forceinline__ void mbar_init(uint32_t a, uint32_t count) {
    asm volatile("mbarrier.init.shared::cta.b64 [%0], %1;" :: "r"(a), "r"(count) : "memory");
}
__device__ __forceinline__ void mbar_arrive(uint32_t a) {
    asm volatile("mbarrier.arrive.release.cta.shared::cta.b64 _, [%0];" :: "r"(a) : "memory");
}
// per-thread: arrive on mbarrier when all of this thread's prior cp.async complete
__device__ __forceinline__ void cp_mbar_arrive(uint32_t a) {
    asm volatile("cp.async.mbarrier.arrive.noinc.shared::cta.b64 [%0];" :: "r"(a) : "memory");
}
__device__ __forceinline__ void mbar_wait(uint32_t a, uint32_t parity) {
    asm volatile(
        "{\n\t"
        ".reg .pred P;\n\t"
        "W%=:\n\t"
        "mbarrier.try_wait.parity.acquire.cta.shared::cta.b64 P, [%0], %1;\n\t"
        "@P bra D%=;\n\t"
        "bra W%=;\n\t"
        "D%=:\n\t"
        "}"
        :: "r"(a), "r"(parity) : "memory");
}

__device__ __forceinline__ void ldsm4(uint32_t* r, uint32_t addr) {
    asm volatile("ldmatrix.sync.aligned.m8n8.x4.shared.b16 {%0,%1,%2,%3}, [%4];"
                 : "=r"(r[0]), "=r"(r[1]), "=r"(r[2]), "=r"(r[3])
                 : "r"(addr));
}

__device__ __forceinline__ void mma_bf16(float* d, const uint32_t* a, const uint32_t* b) {
    asm volatile("mma.sync.aligned.m16n8k16.row.col.f32.bf16.bf16.f32 "
                 "{%0,%1,%2,%3}, {%4,%5,%6,%7}, {%8,%9}, {%0,%1,%2,%3};"
                 : "+f"(d[0]), "+f"(d[1]), "+f"(d[2]), "+f"(d[3])
                 : "r"(a[0]), "r"(a[1]), "r"(a[2]), "r"(a[3]), "r"(b[0]), "r"(b[1]));
}

// ---------------- fused conversion kernel (int8-valued -> bf16, exact) ----------------
#define CVT_XBLOCKS 4096
#define CVT_WBLOCKS 2048

__global__ void __launch_bounds__(512) cvt_fused_kernel(const int4* __restrict__ x,
                                                        const float4* __restrict__ w) {
    const unsigned b = blockIdx.x;
    if (b < CVT_XBLOCKS) {
        const size_t base = (size_t)b * 2048 + threadIdx.x;
        int4 v[4];
        #pragma unroll
        for (int k = 0; k < 4; k++) v[k] = x[base + (size_t)k * 512];
        #pragma unroll
        for (int k = 0; k < 4; k++) {
            union { __nv_bfloat162 h2[2]; uint2 u; } o;
            o.h2[0] = __floats2bfloat162_rn((float)v[k].x, (float)v[k].y);
            o.h2[1] = __floats2bfloat162_rn((float)v[k].z, (float)v[k].w);
            reinterpret_cast<uint2*>(g_A)[base + (size_t)k * 512] = o.u;
        }
    } else {
        const size_t base = (size_t)(b - CVT_XBLOCKS) * 2048 + threadIdx.x;
        float4 v[4];
        #pragma unroll
        for (int k = 0; k < 4; k++) v[k] = w[base + (size_t)k * 512];
        #pragma unroll
        for (int k = 0; k < 4; k++) {
            union { __nv_bfloat162 h2[2]; uint2 u; } o;
            o.h2[0] = __floats2bfloat162_rn(v[k].x, v[k].y);
            o.h2[1] = __floats2bfloat162_rn(v[k].z, v[k].w);
            reinterpret_cast<uint2*>(g_B)[base + (size_t)k * 512] = o.u;
        }
    }
}

// ---------------- GEMM kernel ----------------
__device__ __forceinline__ int clip8(int v) {
    return v < -128 ? -128 : (v > 127 ? 127 : v);
}

__global__ void __launch_bounds__(THREADS, 2)
hmma_gemm_kernel(const float* __restrict__ bias,
                 const float* __restrict__ alpha_p,
                 float* __restrict__ out) {
    extern __shared__ int8_t smem[];
    __shared__ __align__(8) unsigned long long s_mbar[2 * STAGES]; // full[0..2], empty[0..2]
    const uint32_t sbase  = smem_u32(smem);
    const uint32_t mbbase = smem_u32(s_mbar);
    // full(s) = mbbase + 8s ; empty(s) = mbbase + 24 + 8s

    const int tid  = threadIdx.x;
    const int lane = tid & 31;
    const int wid  = tid >> 5;       // 0..7
    const int wm   = wid >> 1;       // 0..3  (M warps, 32 rows each)
    const int wn   = wid & 1;        // 0..1  (N warps, 64 cols each)
    const int m_base = blockIdx.y * BM;
    const int n_base = blockIdx.x * BN;

    if (tid == 0) {
        #pragma unroll
        for (int s = 0; s < STAGES; s++) {
            mbar_init(mbbase + 8u * s, THREADS);     // full: one arrival per thread (cp.async)
            mbar_init(mbbase + 24u + 8u * s, 8);     // empty: one arrival per warp
        }
    }
    __syncthreads();

    float acc[2][8][4];
    #pragma unroll
    for (int i = 0; i < 2; i++)
        #pragma unroll
        for (int j = 0; j < 8; j++)
            #pragma unroll
            for (int k = 0; k < 4; k++) acc[i][j][k] = 0.0f;

    // --- ldmatrix per-thread address components (padded 144B rows) ---
    const uint32_t arow   = (uint32_t)(wm * 32 + (lane & 15));
    const uint32_t akb_hi = (uint32_t)(lane >> 4);                 // 0/1 (8-element k half)
    const uint32_t a_off  = arow * ROWB + akb_hi * 16u;

    const uint32_t brow   = (uint32_t)(wn * 64 + (lane & 7) + ((lane >> 4) << 3));
    const uint32_t bkb_hi = (uint32_t)((lane >> 3) & 1);
    const uint32_t b_off  = brow * ROWB + bkb_hi * 16u;

    // --- one slice of a stage load: 2 chunks (of this thread's 8) ---
    auto load_slice = [&](int kc, int st, int slice) {
        const uint32_t sb = sbase + (uint32_t)st * STAGE_BYTES;
        const int kel = kc * BK;
        #pragma unroll
        for (int q = 0; q < 2; q++) {
            int ch = tid + THREADS * (2 * slice + q);
            if (ch < 1024) {   // A: 1024 chunks (uniform: slice<2)
                int row = ch >> 3, kb = ch & 7;
                cp16(sb + (uint32_t)row * ROWB + (uint32_t)kb * 16u,
                     g_A + (size_t)(m_base + row) * KDIM + kel + kb * 8);
            } else {           // B: 1024 chunks
                int c2 = ch - 1024;
                int row = c2 >> 3, kb = c2 & 7;
                cp16(sb + A_STAGE + (uint32_t)row * ROWB + (uint32_t)kb * 16u,
                     g_B + (size_t)(n_base + row) * KDIM + kel + kb * 8);
            }
        }
    };

    // --- prologue: stages 0 and 1 (fresh empty barriers -> no wait needed) ---
    #pragma unroll
    for (int L = 0; L < 2; L++) {
        #pragma unroll
        for (int i = 0; i < 4; i++) load_slice(L, L, i);
        cp_mbar_arrive(mbbase + 8u * L);             // arrive full[L] when copies land
    }

    // --- mainloop: free-running warps, mbarrier ring sync ---
    for (int c = 0; c < NCHUNK; c++) {
        const int fslot = c % STAGES;
        mbar_wait(mbbase + 8u * fslot, (uint32_t)((c / STAGES) & 1));   // DMA done for chunk c

        const int  L       = c + 2;
        const bool do_load = (L < NCHUNK);
        const int  lslot   = L % STAGES;

        const uint32_t sb     = sbase + (uint32_t)fslot * STAGE_BYTES;
        const uint32_t a_base = sb + a_off;
        const uint32_t b_base = sb + A_STAGE + b_off;

        #pragma unroll
        for (int s = 0; s < 4; s++) {                      // 4 k16 steps per chunk
            if (s == 2 && do_load)                         // mid-chunk: slot (c-1)%3 free?
                mbar_wait(mbbase + 24u + 8u * lslot, (uint32_t)(1 ^ ((L / STAGES) & 1)));

            uint32_t af[2][4];
            uint32_t bf[2][4];
            ldsm4(af[0], a_base + (uint32_t)s * 32u);
            ldsm4(bf[0], b_base + (uint32_t)s * 32u);
            ldsm4(af[1], a_base + (uint32_t)s * 32u + 16u * ROWB);
            #pragma unroll
            for (int j = 0; j < 4; j++) {                  // 4 n16 pairs = 64 n
                if (j < 3)
                    ldsm4(bf[(j + 1) & 1],
                          b_base + (uint32_t)s * 32u + (uint32_t)(j + 1) * (16u * ROWB));
                const uint32_t* b = bf[j & 1];
                mma_bf16(acc[0][2 * j],     af[0], b);
                mma_bf16(acc[0][2 * j + 1], af[0], b + 2);
                mma_bf16(acc[1][2 * j],     af[1], b);
                mma_bf16(acc[1][2 * j + 1], af[1], b + 2);
            }
            if (do_load) {                                 // 2 slices each at s=2,3
                if (s == 2) { load_slice(L, lslot, 0); load_slice(L, lslot, 1); }
                else if (s == 3) { load_slice(L, lslot, 2); load_slice(L, lslot, 3); }
            }
        }
        if (do_load) cp_mbar_arrive(mbbase + 8u * lslot);  // arrive full[L] on completion
        if (lane == 0) mbar_arrive(mbbase + 24u + 8u * fslot);  // this warp done reading slot
    }

    // --- epilogue: y = clip(round_half_even(acc*alpha + bias)), stored as FLOAT32 ---
    const float alphav = *alpha_p;
    const int g = lane >> 2, t = lane & 3;
    #pragma unroll
    for (int i = 0; i < 2; i++) {
        const size_t row0 = (size_t)(m_base + wm * 32 + i * 16 + g);
        #pragma unroll
        for (int j = 0; j < 8; j++) {
            const int nc = n_base + wn * 64 + j * 8 + 2 * t;
            const float b0 = __ldg(bias + nc);
            const float b1 = __ldg(bias + nc + 1);
            const float* a = acc[i][j];
            int v0 = clip8(__float2int_rn(__fadd_rn(__fmul_rn(a[0], alphav), b0)));
            int v1 = clip8(__float2int_rn(__fadd_rn(__fmul_rn(a[1], alphav), b1)));
            int v2 = clip8(__float2int_rn(__fadd_rn(__fmul_rn(a[2], alphav), b0)));
            int v3 = clip8(__float2int_rn(__fadd_rn(__fmul_rn(a[3], alphav), b1)));
            float2 lo = make_float2((float)v0, (float)v1);
            float2 hi = make_float2((float)v2, (float)v3);
            *reinterpret_cast<float2*>(out + row0 * NDIM + nc) = lo;
            *reinterpret_cast<float2*>(out + (row0 + 8) * NDIM + nc) = hi;
        }
    }
}

// ---------------- host launch ----------------
extern "C" void kernel_launch(void* const* d_in, const int* in_sizes, int n_in,
                              void* d_out, int out_size) {
    const int*   x     = (const int*)d_in[0];
    const float* w     = (const float*)d_in[1];
    const float* bias  = (const float*)d_in[2];
    const float* alpha = (const float*)d_in[3];
    float*       out   = (float*)d_out;

    // single fused bf16 conversion launch (x + w)
    cvt_fused_kernel<<<CVT_XBLOCKS + CVT_WBLOCKS, 512>>>((const int4*)x, (const float4*)w);

    // set every call (non-stream API, capture-safe; no static guards per harness rules)
    cudaFuncSetAttribute(hmma_gemm_kernel,
                         cudaFuncAttributeMaxDynamicSharedMemorySize, SMEM_DYN);

    dim3 grid(NDIM / BN, MDIM / BM);   // (32, 64) = 2048 CTAs
    hmma_gemm_kernel<<<grid, THREADS, SMEM_DYN>>>(bias, alpha, out);
}